// round 5
// baseline (speedup 1.0000x reference)
#include <cuda_runtime.h>
#include <cuda_fp16.h>
#include <math.h>

#define NN 20000
#define NE 320000
#define DD 128
#define DD3 384
#define LNUM 3

// ---------------- scratch (static device globals) ----------------
__device__ __half g_filters[(size_t)NE * DD3];  // CSR-permuted, fp16
__device__ float g_dir[(size_t)NE * 4];         // CSR-permuted
__device__ int   g_src[NE];                      // CSR-permuted source node j
__device__ int   g_slot[NE];                     // edge id -> CSR slot
__device__ float g_q[(size_t)NN * DD];
__device__ float g_h[(size_t)NN * DD];
__device__ __half g_x[(size_t)NN * DD3];        // fp16 message features
__device__ float g_mu[(size_t)NN * DD3];
__device__ float g_mu2[(size_t)NN * DD3];
__device__ float g_mumix[(size_t)NN * 768];
__device__ float g_ctx[(size_t)NN * 256];
__device__ float g_dot[(size_t)NN * DD];
__device__ float g_xm[(size_t)NN * DD3];
__device__ int g_cnt[NN];
__device__ int g_rowptr[NN + 1];

__device__ __forceinline__ float siluf(float x) { return x / (1.0f + expf(-x)); }
__device__ __forceinline__ float clip5(float x) { return fminf(fmaxf(x, -5.0f), 5.0f); }

__device__ __forceinline__ unsigned f2tf32(float f)
{
    unsigned r;
    asm("cvt.rna.tf32.f32 %0, %1;" : "=r"(r) : "f"(f));
    return r;
}

__device__ __forceinline__ void mma_tf32(float* c, const unsigned* a, const unsigned* b)
{
    asm volatile(
        "mma.sync.aligned.m16n8k8.row.col.f32.tf32.tf32.f32 "
        "{%0,%1,%2,%3}, {%4,%5,%6,%7}, {%8,%9}, {%0,%1,%2,%3};"
        : "+f"(c[0]), "+f"(c[1]), "+f"(c[2]), "+f"(c[3])
        : "r"(a[0]), "r"(a[1]), "r"(a[2]), "r"(a[3]), "r"(b[0]), "r"(b[1]));
}

// ---------------- TF32 tensor-core GEMM: C = act(A[M,K] @ B[K,Nc] + bias) ----------------
// BM=128, BN=128, BK=16. 256 threads = 8 warps 2(M)x4(N); warp tile 64x32.
// A tile stored in mma-fragment order (uint4 per fragment); tf32 convert at store.
// K % 16 == 0, Nc % 128 == 0.
#define BS_STRIDE 136
template<int ACT, bool OUTH>
__global__ __launch_bounds__(256) void tgemm(const float* __restrict__ A,
                                             const float* __restrict__ B,
                                             const float* __restrict__ bias,
                                             float* __restrict__ C,
                                             int M, int K, int Nc)
{
    // As_p layout (words): kc8*1024 + r16*128 + g*16 + tg*4 + comp
    // comp = h + 2*khalf ; fragment = uint4 at (kc8,r16,g,tg)
    __shared__ unsigned As_p[2][2048];
    __shared__ unsigned Bs[2][16][BS_STRIDE];
    int tid = threadIdx.x;
    int wid = tid >> 5, lane = tid & 31;
    int g = lane >> 2, tg = lane & 3;
    int wm = wid & 1, wn = wid >> 1;
    int row0 = blockIdx.y * 128, col0 = blockIdx.x * 128;

    int arow = tid >> 1, acol = (tid & 1) * 8;
    int kc8s = tid & 1;
    int r16s = arow >> 4, gs = arow & 7, hs = (arow >> 3) & 1;
    int abase = kc8s * 1024 + r16s * 128 + gs * 16 + hs;

    int brow = tid >> 4, bcol = (tid & 15) * 8;
    bool aval = (row0 + arow) < M;
    const float* Aptr = A + (size_t)(row0 + arow) * K + acol;
    const float* Bptr = B + (size_t)brow * Nc + col0 + bcol;

    float acc[4][4][4];
#pragma unroll
    for (int mt = 0; mt < 4; mt++)
#pragma unroll
        for (int nt = 0; nt < 4; nt++)
#pragma unroll
            for (int r = 0; r < 4; r++) acc[mt][nt][r] = 0.0f;

    // prologue: tile 0 -> buffer 0
    {
        float4 a0 = make_float4(0.f, 0.f, 0.f, 0.f), a1 = a0;
        if (aval) { a0 = *(const float4*)(Aptr); a1 = *(const float4*)(Aptr + 4); }
        float va[8] = {a0.x, a0.y, a0.z, a0.w, a1.x, a1.y, a1.z, a1.w};
        unsigned* ap = &As_p[0][abase];
#pragma unroll
        for (int kk = 0; kk < 8; kk++)
            ap[(kk & 3) * 4 + (kk >> 2) * 2] = f2tf32(va[kk]);
        float4 b0 = *(const float4*)(Bptr);
        float4 b1 = *(const float4*)(Bptr + 4);
        uint4 u0 = make_uint4(f2tf32(b0.x), f2tf32(b0.y), f2tf32(b0.z), f2tf32(b0.w));
        uint4 u1 = make_uint4(f2tf32(b1.x), f2tf32(b1.y), f2tf32(b1.z), f2tf32(b1.w));
        *(uint4*)(&Bs[0][brow][bcol])     = u0;
        *(uint4*)(&Bs[0][brow][bcol + 4]) = u1;
    }
    __syncthreads();

    int nt_tiles = K >> 4;
    for (int t = 0; t < nt_tiles; t++) {
        int cur = t & 1, nxt = cur ^ 1;
        float4 na0, na1, nb0, nb1;
        if (t + 1 < nt_tiles) {
            if (aval) {
                na0 = *(const float4*)(Aptr + (t + 1) * 16);
                na1 = *(const float4*)(Aptr + (t + 1) * 16 + 4);
            } else { na0 = make_float4(0.f,0.f,0.f,0.f); na1 = na0; }
            const float* bp = Bptr + (size_t)(t + 1) * 16 * Nc;
            nb0 = *(const float4*)(bp);
            nb1 = *(const float4*)(bp + 4);
        }
#pragma unroll
        for (int kc = 0; kc < 16; kc += 8) {
            int kc8 = kc >> 3;
            uint4 ar[4];
            unsigned br[4][2];
#pragma unroll
            for (int mt = 0; mt < 4; mt++)
                ar[mt] = *(const uint4*)(&As_p[cur][kc8 * 1024 + (wm * 4 + mt) * 128 + g * 16 + tg * 4]);
#pragma unroll
            for (int nt = 0; nt < 4; nt++) {
                int nc0 = wn * 32 + nt * 8;
                br[nt][0] = Bs[cur][kc + tg][nc0 + g];
                br[nt][1] = Bs[cur][kc + tg + 4][nc0 + g];
            }
#pragma unroll
            for (int mt = 0; mt < 4; mt++)
#pragma unroll
                for (int nt = 0; nt < 4; nt++)
                    mma_tf32(acc[mt][nt], (const unsigned*)&ar[mt], br[nt]);
        }
        if (t + 1 < nt_tiles) {
            float va[8] = {na0.x, na0.y, na0.z, na0.w, na1.x, na1.y, na1.z, na1.w};
            unsigned* ap = &As_p[nxt][abase];
#pragma unroll
            for (int kk = 0; kk < 8; kk++)
                ap[(kk & 3) * 4 + (kk >> 2) * 2] = f2tf32(va[kk]);
            uint4 u0 = make_uint4(f2tf32(nb0.x), f2tf32(nb0.y), f2tf32(nb0.z), f2tf32(nb0.w));
            uint4 u1 = make_uint4(f2tf32(nb1.x), f2tf32(nb1.y), f2tf32(nb1.z), f2tf32(nb1.w));
            *(uint4*)(&Bs[nxt][brow][bcol])     = u0;
            *(uint4*)(&Bs[nxt][brow][bcol + 4]) = u1;
        }
        __syncthreads();
    }

    // epilogue
#pragma unroll
    for (int mt = 0; mt < 4; mt++) {
#pragma unroll
        for (int nt = 0; nt < 4; nt++) {
            int col = col0 + wn * 32 + nt * 8 + 2 * tg;
            float bb0 = 0.f, bb1 = 0.f;
            if (bias) { bb0 = bias[col]; bb1 = bias[col + 1]; }
#pragma unroll
            for (int half = 0; half < 2; half++) {
                int row = row0 + wm * 64 + mt * 16 + g + half * 8;
                if (row >= M) continue;
                float v0 = acc[mt][nt][half * 2 + 0] + bb0;
                float v1 = acc[mt][nt][half * 2 + 1] + bb1;
                if (ACT == 1) { v0 = siluf(v0); v1 = siluf(v1); }
                if (OUTH) {
                    __half2* o = (__half2*)((__half*)C + (size_t)row * Nc + col);
                    *o = __floats2half2_rn(v0, v1);
                } else {
                    *(float2*)(C + (size_t)row * Nc + col) = make_float2(v0, v1);
                }
            }
        }
    }
}

// ---------------- CSR build ----------------
__global__ void init_bufs()
{
    int idx = blockIdx.x * blockDim.x + threadIdx.x;
    if (idx < NN * DD3) g_mu[idx] = 0.f;
    if (idx < NN) g_cnt[idx] = 0;
}

__global__ void csr_count(const int* __restrict__ ei)
{
    int e = blockIdx.x * blockDim.x + threadIdx.x;
    if (e < NE) atomicAdd(&g_cnt[ei[e]], 1);
}

__global__ __launch_bounds__(1024) void csr_scan()
{
    __shared__ int part[1024];
    int t = threadIdx.x;
    const int CH = (NN + 1023) / 1024;
    int base = t * CH;
    int s = 0;
    for (int k = 0; k < CH; k++) {
        int n = base + k;
        if (n < NN) s += g_cnt[n];
    }
    part[t] = s;
    __syncthreads();
    for (int off = 1; off < 1024; off <<= 1) {
        int v = (t >= off) ? part[t - off] : 0;
        __syncthreads();
        part[t] += v;
        __syncthreads();
    }
    int run = (t == 0) ? 0 : part[t - 1];
    for (int k = 0; k < CH; k++) {
        int n = base + k;
        if (n < NN) {
            g_rowptr[n] = run;
            run += g_cnt[n];
            g_cnt[n] = 0;
        }
    }
    if (t == 1023) g_rowptr[NN] = run;
}

__global__ void csr_fill(const int* __restrict__ ei)
{
    int e = blockIdx.x * blockDim.x + threadIdx.x;
    if (e < NE) {
        int i = ei[e];
        int pos = atomicAdd(&g_cnt[i], 1);
        int slot = g_rowptr[i] + pos;
        g_slot[e] = slot;
        g_src[slot] = ei[NE + e];
    }
}

// ---------------- per-edge geometry + RBF filters (fp16, written to CSR slot) ----------------
__global__ __launch_bounds__(256) void edge_pre(const float* __restrict__ pos,
                                                const int* __restrict__ ei,
                                                const float* __restrict__ fw,
                                                const float* __restrict__ fb)
{
    int e = blockIdx.x * 8 + (threadIdx.x >> 5);
    if (e >= NE) return;
    int lane = threadIdx.x & 31;
    int i = ei[e], j = ei[NE + e];
    int slot = g_slot[e];
    float rx = pos[j * 3 + 0] - pos[i * 3 + 0];
    float ry = pos[j * 3 + 1] - pos[i * 3 + 1];
    float rz = pos[j * 3 + 2] - pos[i * 3 + 2];
    float d = sqrtf(rx * rx + ry * ry + rz * rz);
    d = fmaxf(d, 1e-8f);
    float dv = (lane == 0) ? rx : ((lane == 1) ? ry : rz);
    if (lane < 3) g_dir[(size_t)slot * 4 + lane] = dv / d;
    if (lane == 3) g_dir[(size_t)slot * 4 + 3] = 0.f;

    const float spacing = 5.0f / 63.0f;
    const float coeff = -0.5f / (spacing * spacing);
    float xc = fminf(d * 0.2f, 1.0f);
    float fcut = (xc < 1.0f) ? 0.5f * (cospif(xc) + 1.0f) : 0.0f;

    float4 acc0 = make_float4(0.f, 0.f, 0.f, 0.f), acc1 = acc0, acc2 = acc0;
    if (fcut > 0.0f) {
        int k0 = (int)rintf(d / spacing);
        int lo = max(0, k0 - 8), hi = min(63, k0 + 8);
        const float4* fw4 = (const float4*)fw;
        for (int k = lo; k <= hi; k++) {
            float t = d - (float)k * spacing;
            float p = expf(coeff * t * t);
            float4 w0 = fw4[k * 96 + lane];
            float4 w1 = fw4[k * 96 + lane + 32];
            float4 w2 = fw4[k * 96 + lane + 64];
            acc0.x += p * w0.x; acc0.y += p * w0.y; acc0.z += p * w0.z; acc0.w += p * w0.w;
            acc1.x += p * w1.x; acc1.y += p * w1.y; acc1.z += p * w1.z; acc1.w += p * w1.w;
            acc2.x += p * w2.x; acc2.y += p * w2.y; acc2.z += p * w2.z; acc2.w += p * w2.w;
        }
    }
    const float4* fb4 = (const float4*)fb;
    __half2* outh = (__half2*)(g_filters + (size_t)slot * DD3);
#pragma unroll
    for (int grp = 0; grp < 3; grp++) {
        float4 a = (grp == 0) ? acc0 : ((grp == 1) ? acc1 : acc2);
        float4 b = fb4[lane + 32 * grp];
        float v0 = clip5((a.x + b.x) * fcut);
        float v1 = clip5((a.y + b.y) * fcut);
        float v2 = clip5((a.z + b.z) * fcut);
        float v3 = clip5((a.w + b.w) * fcut);
        int base2 = (grp * 128 + lane * 4) >> 1;
        outh[base2]     = __floats2half2_rn(v0, v1);
        outh[base2 + 1] = __floats2half2_rn(v2, v3);
    }
}

// ---------------- CSR gather of edge messages ----------------
__global__ __launch_bounds__(128) void gather_msg(const float* __restrict__ mu_in,
                                                  float* __restrict__ mu_out)
{
    int n = blockIdx.x, c = threadIdx.x;
    int s = g_rowptr[n], t = g_rowptr[n + 1];
    float aq = 0.f, m0 = 0.f, m1 = 0.f, m2 = 0.f;
    for (int k = s; k < t; k++) {
        int j = __ldg(&g_src[k]);
        const __half* f  = g_filters + (size_t)k * DD3;
        const __half* xj = g_x + (size_t)j * DD3;
        float dq    = __half2float(xj[c])          * __half2float(f[c]);
        float dmuR  = __half2float(xj[DD + c])     * __half2float(f[DD + c]);
        float dmumu = __half2float(xj[2 * DD + c]) * __half2float(f[2 * DD + c]);
        float4 dv = *(const float4*)(g_dir + (size_t)k * 4);
        const float* muj = mu_in + (size_t)j * DD3;
        aq += dq;
        m0 += dmuR * dv.x + dmumu * muj[c];
        m1 += dmuR * dv.y + dmumu * muj[DD + c];
        m2 += dmuR * dv.z + dmumu * muj[2 * DD + c];
    }
    g_q[(size_t)n * DD + c] += aq;
    const float* mui = mu_in + (size_t)n * DD3;
    float* muo = mu_out + (size_t)n * DD3;
    muo[c]          = mui[c] + m0;
    muo[DD + c]     = mui[DD + c] + m1;
    muo[2 * DD + c] = mui[2 * DD + c] + m2;
}

// ---------------- mu_Vn / dot(mu_V,mu_W) / ctx ----------------
__global__ __launch_bounds__(128) void reduce_mix()
{
    int n = blockIdx.x, c = threadIdx.x;
    size_t base = (size_t)n * 768;
    float v0 = g_mumix[base + c],        w0 = g_mumix[base + 128 + c];
    float v1 = g_mumix[base + 256 + c],  w1 = g_mumix[base + 384 + c];
    float v2 = g_mumix[base + 512 + c],  w2 = g_mumix[base + 640 + c];
    float vn = sqrtf(v0 * v0 + v1 * v1 + v2 * v2 + 1e-8f);
    g_ctx[(size_t)n * 256 + c]       = g_q[(size_t)n * DD + c];
    g_ctx[(size_t)n * 256 + 128 + c] = vn;
    g_dot[(size_t)n * DD + c] = v0 * w0 + v1 * w1 + v2 * w2;
}

// ---------------- q,mu self-update ----------------
__global__ __launch_bounds__(128) void update_node(float* __restrict__ mu)
{
    int n = blockIdx.x, c = threadIdx.x;
    size_t xb = (size_t)n * DD3;
    float dq_i  = g_xm[xb + c];
    float dmu_i = g_xm[xb + DD + c];
    float dqmu  = g_xm[xb + 2 * DD + c];
    g_q[(size_t)n * DD + c] += dq_i + dqmu * g_dot[(size_t)n * DD + c];
    size_t mb = (size_t)n * 768;
#pragma unroll
    for (int a = 0; a < 3; a++)
        mu[(size_t)n * DD3 + a * DD + c] += dmu_i * g_mumix[mb + a * 256 + 128 + c];
}

// ---------------- final layernorm -> tanh ----------------
__global__ __launch_bounds__(128) void layernorm_out(const float* __restrict__ lng,
                                                     const float* __restrict__ lnb,
                                                     float* __restrict__ out)
{
    int n = blockIdx.x, c = threadIdx.x;
    float v = clip5(g_q[(size_t)n * DD + c]);
    float s = v, s2 = v * v;
#pragma unroll
    for (int o = 16; o; o >>= 1) {
        s  += __shfl_xor_sync(0xffffffffu, s, o);
        s2 += __shfl_xor_sync(0xffffffffu, s2, o);
    }
    __shared__ float sh[4], sh2[4];
    int w = c >> 5, l = c & 31;
    if (l == 0) { sh[w] = s; sh2[w] = s2; }
    __syncthreads();
    float S  = sh[0] + sh[1] + sh[2] + sh[3];
    float S2 = sh2[0] + sh2[1] + sh2[2] + sh2[3];
    float mean = S * (1.0f / 128.0f);
    float var  = S2 * (1.0f / 128.0f) - mean * mean;
    float y = (v - mean) * rsqrtf(var + 1e-5f) * lng[c] + lnb[c];
    out[(size_t)n * DD + c] = tanhf(y);
}

// ---------------- final mu_node gather + pos_attr (fused) ----------------
__global__ __launch_bounds__(128) void pos_gather(const float* __restrict__ mu,
                                                  const float* __restrict__ mpw,
                                                  float* __restrict__ out)
{
    int n = blockIdx.x, c = threadIdx.x;
    int s = g_rowptr[n], t = g_rowptr[n + 1];
    float s0 = 0.f, s1 = 0.f, s2 = 0.f;
    for (int k = s; k < t; k++) {
        int j = __ldg(&g_src[k]);
        const float* muj = mu + (size_t)j * DD3;
        s0 += muj[c];
        s1 += muj[DD + c];
        s2 += muj[2 * DD + c];
    }
    float w = mpw[c];
    s0 = clip5(s0) * w;
    s1 = clip5(s1) * w;
    s2 = clip5(s2) * w;
#pragma unroll
    for (int o = 16; o; o >>= 1) {
        s0 += __shfl_xor_sync(0xffffffffu, s0, o);
        s1 += __shfl_xor_sync(0xffffffffu, s1, o);
        s2 += __shfl_xor_sync(0xffffffffu, s2, o);
    }
    __shared__ float sh[4][3];
    int wd = c >> 5, l = c & 31;
    if (l == 0) { sh[wd][0] = s0; sh[wd][1] = s1; sh[wd][2] = s2; }
    __syncthreads();
    if (c < 3) {
        float v = sh[0][c] + sh[1][c] + sh[2][c] + sh[3][c];
        out[(size_t)n * 3 + c] = clip5(v);
    }
}

// ---------------- launch ----------------
extern "C" void kernel_launch(void* const* d_in, const int* in_sizes, int n_in,
                              void* d_out, int out_size)
{
    const float* z      = (const float*)d_in[0];
    const float* pos    = (const float*)d_in[1];
    const int*   ei     = (const int*)  d_in[2];
    const float* in_w   = (const float*)d_in[3];
    const float* in_b   = (const float*)d_in[4];
    const float* filt_w = (const float*)d_in[5];
    const float* filt_b = (const float*)d_in[6];
    const float* iw1    = (const float*)d_in[7];
    const float* ib1    = (const float*)d_in[8];
    const float* iw2    = (const float*)d_in[9];
    const float* ib2    = (const float*)d_in[10];
    const float* mmw    = (const float*)d_in[11];
    const float* mw1    = (const float*)d_in[12];
    const float* mb1    = (const float*)d_in[13];
    const float* mw2    = (const float*)d_in[14];
    const float* mb2    = (const float*)d_in[15];
    const float* mpw    = (const float*)d_in[16];
    const float* lng    = (const float*)d_in[17];
    const float* lnb    = (const float*)d_in[18];
    float* out = (float*)d_out;

    float *p_q, *p_h, *p_mu, *p_mu2, *p_mumix, *p_ctx, *p_xm;
    __half* p_x;
    cudaGetSymbolAddress((void**)&p_q,     g_q);
    cudaGetSymbolAddress((void**)&p_h,     g_h);
    cudaGetSymbolAddress((void**)&p_x,     g_x);
    cudaGetSymbolAddress((void**)&p_mu,    g_mu);
    cudaGetSymbolAddress((void**)&p_mu2,   g_mu2);
    cudaGetSymbolAddress((void**)&p_mumix, g_mumix);
    cudaGetSymbolAddress((void**)&p_ctx,   g_ctx);
    cudaGetSymbolAddress((void**)&p_xm,    g_xm);

    int gy_n  = (NN + 127) / 128;        // 157
    int gy_3n = (3 * NN + 127) / 128;    // 469

    init_bufs<<<(NN * DD3 + 255) / 256, 256>>>();
    csr_count<<<(NE + 255) / 256, 256>>>(ei);
    csr_scan<<<1, 1024>>>();
    csr_fill<<<(NE + 255) / 256, 256>>>(ei);

    tgemm<1,false><<<dim3(1, gy_n), 256>>>(z, in_w, in_b, p_q, NN, 64, DD);
    edge_pre<<<(NE + 7) / 8, 256>>>(pos, ei, filt_w, filt_b);

    float* mu_in = p_mu;
    float* mu_out = p_mu2;
    for (int l = 0; l < LNUM; l++) {
        tgemm<1,false><<<dim3(1, gy_n), 256>>>(p_q, iw1 + (size_t)l * DD * DD, ib1 + (size_t)l * DD,
                                               p_h, NN, DD, DD);
        tgemm<0,true><<<dim3(3, gy_n), 256>>>(p_h, iw2 + (size_t)l * DD * DD3, ib2 + (size_t)l * DD3,
                                              (float*)p_x, NN, DD, DD3);
        gather_msg<<<NN, 128>>>(mu_in, mu_out);
        tgemm<0,false><<<dim3(2, gy_3n), 256>>>(mu_out, mmw + (size_t)l * DD * 256, nullptr,
                                                p_mumix, 3 * NN, DD, 256);
        reduce_mix<<<NN, 128>>>();
        tgemm<1,false><<<dim3(1, gy_n), 256>>>(p_ctx, mw1 + (size_t)l * 256 * DD, mb1 + (size_t)l * DD,
                                               p_h, NN, 256, DD);
        tgemm<0,false><<<dim3(3, gy_n), 256>>>(p_h, mw2 + (size_t)l * DD * DD3, mb2 + (size_t)l * DD3,
                                               p_xm, NN, DD, DD3);
        update_node<<<NN, 128>>>(mu_out);
        float* tmp = mu_in; mu_in = mu_out; mu_out = tmp;
    }

    layernorm_out<<<NN, 128>>>(lng, lnb, out);
    pos_gather<<<NN, 128>>>(mu_in, mpw, out + (size_t)NN * DD);
}

// round 6
// speedup vs baseline: 1.0748x; 1.0748x over previous
#include <cuda_runtime.h>
#include <cuda_fp16.h>
#include <math.h>

#define NN 20000
#define NE 320000
#define DD 128
#define DD3 384
#define LNUM 3

// ---------------- scratch (static device globals) ----------------
__device__ __half g_filters[(size_t)NE * DD3];  // CSR-permuted, fp16, streaming
__device__ float g_dir[(size_t)NE * 4];         // CSR-permuted
__device__ int   g_src[NE];                      // CSR-permuted source node j
__device__ int   g_slot[NE];                     // edge id -> CSR slot
__device__ float g_q[(size_t)NN * DD];
__device__ float g_h[(size_t)NN * DD];
__device__ float g_x[(size_t)NN * DD3];
__device__ float g_mu[(size_t)NN * DD3];
__device__ float g_mu2[(size_t)NN * DD3];
__device__ float g_mumix[(size_t)NN * 768];
__device__ float g_ctx[(size_t)NN * 256];
__device__ float g_dot[(size_t)NN * DD];
__device__ float g_xm[(size_t)NN * DD3];
__device__ int g_cnt[NN];
__device__ int g_rowptr[NN + 1];

__device__ __forceinline__ float siluf(float x) { return x / (1.0f + expf(-x)); }
__device__ __forceinline__ float clip5(float x) { return fminf(fmaxf(x, -5.0f), 5.0f); }

__device__ __forceinline__ unsigned f2tf32(float f)
{
    unsigned r;
    asm("cvt.rna.tf32.f32 %0, %1;" : "=r"(r) : "f"(f));
    return r;
}

__device__ __forceinline__ void mma_tf32(float* c, const unsigned* a, const unsigned* b)
{
    asm volatile(
        "mma.sync.aligned.m16n8k8.row.col.f32.tf32.tf32.f32 "
        "{%0,%1,%2,%3}, {%4,%5,%6,%7}, {%8,%9}, {%0,%1,%2,%3};"
        : "+f"(c[0]), "+f"(c[1]), "+f"(c[2]), "+f"(c[3])
        : "r"(a[0]), "r"(a[1]), "r"(a[2]), "r"(a[3]), "r"(b[0]), "r"(b[1]));
}

// ---------------- TF32 tensor-core GEMM: C = act(A[M,K] @ B[K,Nc] + bias) ----------------
// BM=128, BN=128, BK=16. 256 threads = 8 warps in 2(M)x4(N); warp tile 64x32.
// K % 16 == 0, Nc % 128 == 0.  (Round-4 proven version.)
#define AS_STRIDE 20
#define BS_STRIDE 136
template<int ACT>
__global__ __launch_bounds__(256) void tgemm(const float* __restrict__ A,
                                             const float* __restrict__ B,
                                             const float* __restrict__ bias,
                                             float* __restrict__ C,
                                             int M, int K, int Nc)
{
    __shared__ float As[2][128][AS_STRIDE];
    __shared__ float Bs[2][16][BS_STRIDE];
    int tid = threadIdx.x;
    int wid = tid >> 5, lane = tid & 31;
    int g = lane >> 2, tg = lane & 3;
    int wm = wid & 1, wn = wid >> 1;
    int row0 = blockIdx.y * 128, col0 = blockIdx.x * 128;

    int arow = tid >> 1, acol = (tid & 1) * 8;
    int brow = tid >> 4, bcol = (tid & 15) * 8;
    bool aval = (row0 + arow) < M;
    const float* Aptr = A + (size_t)(row0 + arow) * K + acol;
    const float* Bptr = B + (size_t)brow * Nc + col0 + bcol;

    float acc[4][4][4];
#pragma unroll
    for (int mt = 0; mt < 4; mt++)
#pragma unroll
        for (int nt = 0; nt < 4; nt++)
#pragma unroll
            for (int r = 0; r < 4; r++) acc[mt][nt][r] = 0.0f;

    // prologue: tile 0 -> buffer 0
    float4 a0 = make_float4(0.f, 0.f, 0.f, 0.f), a1 = a0;
    if (aval) { a0 = *(const float4*)(Aptr); a1 = *(const float4*)(Aptr + 4); }
    float4 b0 = *(const float4*)(Bptr);
    float4 b1 = *(const float4*)(Bptr + 4);
    *(float4*)(&As[0][arow][acol])     = a0;
    *(float4*)(&As[0][arow][acol + 4]) = a1;
    *(float4*)(&Bs[0][brow][bcol])     = b0;
    *(float4*)(&Bs[0][brow][bcol + 4]) = b1;
    __syncthreads();

    int nt_tiles = K >> 4;
    for (int t = 0; t < nt_tiles; t++) {
        int cur = t & 1, nxt = cur ^ 1;
        float4 na0, na1, nb0, nb1;
        if (t + 1 < nt_tiles) {
            if (aval) {
                na0 = *(const float4*)(Aptr + (t + 1) * 16);
                na1 = *(const float4*)(Aptr + (t + 1) * 16 + 4);
            } else { na0 = make_float4(0.f,0.f,0.f,0.f); na1 = na0; }
            const float* bp = Bptr + (size_t)(t + 1) * 16 * Nc;
            nb0 = *(const float4*)(bp);
            nb1 = *(const float4*)(bp + 4);
        }
#pragma unroll
        for (int kc = 0; kc < 16; kc += 8) {
            unsigned ar[4][4], br[4][2];
#pragma unroll
            for (int mt = 0; mt < 4; mt++) {
                int r = wm * 64 + mt * 16;
                ar[mt][0] = f2tf32(As[cur][r + g][kc + tg]);
                ar[mt][1] = f2tf32(As[cur][r + g + 8][kc + tg]);
                ar[mt][2] = f2tf32(As[cur][r + g][kc + tg + 4]);
                ar[mt][3] = f2tf32(As[cur][r + g + 8][kc + tg + 4]);
            }
#pragma unroll
            for (int nt = 0; nt < 4; nt++) {
                int nc0 = wn * 32 + nt * 8;
                br[nt][0] = f2tf32(Bs[cur][kc + tg][nc0 + g]);
                br[nt][1] = f2tf32(Bs[cur][kc + tg + 4][nc0 + g]);
            }
#pragma unroll
            for (int mt = 0; mt < 4; mt++)
#pragma unroll
                for (int nt = 0; nt < 4; nt++)
                    mma_tf32(acc[mt][nt], ar[mt], br[nt]);
        }
        if (t + 1 < nt_tiles) {
            *(float4*)(&As[nxt][arow][acol])     = na0;
            *(float4*)(&As[nxt][arow][acol + 4]) = na1;
            *(float4*)(&Bs[nxt][brow][bcol])     = nb0;
            *(float4*)(&Bs[nxt][brow][bcol + 4]) = nb1;
        }
        __syncthreads();
    }

    // epilogue
#pragma unroll
    for (int mt = 0; mt < 4; mt++) {
#pragma unroll
        for (int nt = 0; nt < 4; nt++) {
            int col = col0 + wn * 32 + nt * 8 + 2 * tg;
            float bb0 = 0.f, bb1 = 0.f;
            if (bias) { bb0 = bias[col]; bb1 = bias[col + 1]; }
#pragma unroll
            for (int half = 0; half < 2; half++) {
                int row = row0 + wm * 64 + mt * 16 + g + half * 8;
                if (row >= M) continue;
                float v0 = acc[mt][nt][half * 2 + 0] + bb0;
                float v1 = acc[mt][nt][half * 2 + 1] + bb1;
                if (ACT == 1) { v0 = siluf(v0); v1 = siluf(v1); }
                *(float2*)(C + (size_t)row * Nc + col) = make_float2(v0, v1);
            }
        }
    }
}

// ---------------- CSR build ----------------
__global__ void init_bufs()
{
    int idx = blockIdx.x * blockDim.x + threadIdx.x;
    if (idx < NN) g_cnt[idx] = 0;
}

__global__ void csr_count(const int* __restrict__ ei)
{
    int e = blockIdx.x * blockDim.x + threadIdx.x;
    if (e < NE) atomicAdd(&g_cnt[ei[e]], 1);
}

__global__ __launch_bounds__(1024) void csr_scan()
{
    __shared__ int part[1024];
    int t = threadIdx.x;
    const int CH = (NN + 1023) / 1024;
    int base = t * CH;
    int s = 0;
    for (int k = 0; k < CH; k++) {
        int n = base + k;
        if (n < NN) s += g_cnt[n];
    }
    part[t] = s;
    __syncthreads();
    for (int off = 1; off < 1024; off <<= 1) {
        int v = (t >= off) ? part[t - off] : 0;
        __syncthreads();
        part[t] += v;
        __syncthreads();
    }
    int run = (t == 0) ? 0 : part[t - 1];
    for (int k = 0; k < CH; k++) {
        int n = base + k;
        if (n < NN) {
            g_rowptr[n] = run;
            run += g_cnt[n];
            g_cnt[n] = 0;
        }
    }
    if (t == 1023) g_rowptr[NN] = run;
}

__global__ void csr_fill(const int* __restrict__ ei)
{
    int e = blockIdx.x * blockDim.x + threadIdx.x;
    if (e < NE) {
        int i = ei[e];
        int pos = atomicAdd(&g_cnt[i], 1);
        int slot = g_rowptr[i] + pos;
        g_slot[e] = slot;
        g_src[slot] = ei[NE + e];
    }
}

// ---------------- per-edge geometry + RBF filters (fp16, streaming stores) ----------------
__global__ __launch_bounds__(256) void edge_pre(const float* __restrict__ pos,
                                                const int* __restrict__ ei,
                                                const float* __restrict__ fw,
                                                const float* __restrict__ fb)
{
    int e = blockIdx.x * 8 + (threadIdx.x >> 5);
    if (e >= NE) return;
    int lane = threadIdx.x & 31;
    int i = ei[e], j = ei[NE + e];
    int slot = g_slot[e];
    float rx = pos[j * 3 + 0] - pos[i * 3 + 0];
    float ry = pos[j * 3 + 1] - pos[i * 3 + 1];
    float rz = pos[j * 3 + 2] - pos[i * 3 + 2];
    float d = sqrtf(rx * rx + ry * ry + rz * rz);
    d = fmaxf(d, 1e-8f);
    float dv = (lane == 0) ? rx : ((lane == 1) ? ry : rz);
    if (lane < 3) g_dir[(size_t)slot * 4 + lane] = dv / d;
    if (lane == 3) g_dir[(size_t)slot * 4 + 3] = 0.f;

    const float spacing = 5.0f / 63.0f;
    const float coeff = -0.5f / (spacing * spacing);
    float xc = fminf(d * 0.2f, 1.0f);
    float fcut = (xc < 1.0f) ? 0.5f * (cospif(xc) + 1.0f) : 0.0f;

    float4 acc0 = make_float4(0.f, 0.f, 0.f, 0.f), acc1 = acc0, acc2 = acc0;
    if (fcut > 0.0f) {
        int k0 = (int)rintf(d / spacing);
        int lo = max(0, k0 - 8), hi = min(63, k0 + 8);
        const float4* fw4 = (const float4*)fw;
        for (int k = lo; k <= hi; k++) {
            float t = d - (float)k * spacing;
            float p = expf(coeff * t * t);
            float4 w0 = fw4[k * 96 + lane];
            float4 w1 = fw4[k * 96 + lane + 32];
            float4 w2 = fw4[k * 96 + lane + 64];
            acc0.x += p * w0.x; acc0.y += p * w0.y; acc0.z += p * w0.z; acc0.w += p * w0.w;
            acc1.x += p * w1.x; acc1.y += p * w1.y; acc1.z += p * w1.z; acc1.w += p * w1.w;
            acc2.x += p * w2.x; acc2.y += p * w2.y; acc2.z += p * w2.z; acc2.w += p * w2.w;
        }
    }
    const float4* fb4 = (const float4*)fb;
    __half2* outh = (__half2*)(g_filters + (size_t)slot * DD3);
#pragma unroll
    for (int grp = 0; grp < 3; grp++) {
        float4 a = (grp == 0) ? acc0 : ((grp == 1) ? acc1 : acc2);
        float4 b = fb4[lane + 32 * grp];
        float v0 = clip5((a.x + b.x) * fcut);
        float v1 = clip5((a.y + b.y) * fcut);
        float v2 = clip5((a.z + b.z) * fcut);
        float v3 = clip5((a.w + b.w) * fcut);
        int base2 = (grp * 128 + lane * 4) >> 1;
        __stcs(outh + base2,     __floats2half2_rn(v0, v1));
        __stcs(outh + base2 + 1, __floats2half2_rn(v2, v3));
    }
}

// ---------------- CSR gather of edge messages ----------------
// MUZERO: layer 0, mu_in is identically zero -> skip all mu reads.
template<bool MUZERO>
__global__ __launch_bounds__(128) void gather_msg(const float* __restrict__ mu_in,
                                                  float* __restrict__ mu_out)
{
    int n = blockIdx.x, c = threadIdx.x;
    int s = g_rowptr[n], t = g_rowptr[n + 1];
    float aq = 0.f, m0 = 0.f, m1 = 0.f, m2 = 0.f;
    for (int k = s; k < t; k++) {
        int j = __ldg(&g_src[k]);
        const __half* f = g_filters + (size_t)k * DD3;
        const float* xj = g_x + (size_t)j * DD3;
        float fq    = __half2float(__ldcs(f + c));
        float fR    = __half2float(__ldcs(f + DD + c));
        float fmu   = __half2float(__ldcs(f + 2 * DD + c));
        float dq    = xj[c]          * fq;
        float dmuR  = xj[DD + c]     * fR;
        float dmumu = xj[2 * DD + c] * fmu;
        float4 dv = __ldcs((const float4*)(g_dir + (size_t)k * 4));
        aq += dq;
        if (MUZERO) {
            m0 += dmuR * dv.x;
            m1 += dmuR * dv.y;
            m2 += dmuR * dv.z;
        } else {
            const float* muj = mu_in + (size_t)j * DD3;
            m0 += dmuR * dv.x + dmumu * muj[c];
            m1 += dmuR * dv.y + dmumu * muj[DD + c];
            m2 += dmuR * dv.z + dmumu * muj[2 * DD + c];
        }
    }
    g_q[(size_t)n * DD + c] += aq;
    float* muo = mu_out + (size_t)n * DD3;
    if (MUZERO) {
        muo[c]          = m0;
        muo[DD + c]     = m1;
        muo[2 * DD + c] = m2;
    } else {
        const float* mui = mu_in + (size_t)n * DD3;
        muo[c]          = mui[c] + m0;
        muo[DD + c]     = mui[DD + c] + m1;
        muo[2 * DD + c] = mui[2 * DD + c] + m2;
    }
}

// ---------------- mu_Vn / dot(mu_V,mu_W) / ctx ----------------
__global__ __launch_bounds__(128) void reduce_mix()
{
    int n = blockIdx.x, c = threadIdx.x;
    size_t base = (size_t)n * 768;
    float v0 = g_mumix[base + c],        w0 = g_mumix[base + 128 + c];
    float v1 = g_mumix[base + 256 + c],  w1 = g_mumix[base + 384 + c];
    float v2 = g_mumix[base + 512 + c],  w2 = g_mumix[base + 640 + c];
    float vn = sqrtf(v0 * v0 + v1 * v1 + v2 * v2 + 1e-8f);
    g_ctx[(size_t)n * 256 + c]       = g_q[(size_t)n * DD + c];
    g_ctx[(size_t)n * 256 + 128 + c] = vn;
    g_dot[(size_t)n * DD + c] = v0 * w0 + v1 * w1 + v2 * w2;
}

// ---------------- q,mu self-update ----------------
__global__ __launch_bounds__(128) void update_node(float* __restrict__ mu)
{
    int n = blockIdx.x, c = threadIdx.x;
    size_t xb = (size_t)n * DD3;
    float dq_i  = g_xm[xb + c];
    float dmu_i = g_xm[xb + DD + c];
    float dqmu  = g_xm[xb + 2 * DD + c];
    g_q[(size_t)n * DD + c] += dq_i + dqmu * g_dot[(size_t)n * DD + c];
    size_t mb = (size_t)n * 768;
#pragma unroll
    for (int a = 0; a < 3; a++)
        mu[(size_t)n * DD3 + a * DD + c] += dmu_i * g_mumix[mb + a * 256 + 128 + c];
}

// ---------------- final layernorm -> tanh ----------------
__global__ __launch_bounds__(128) void layernorm_out(const float* __restrict__ lng,
                                                     const float* __restrict__ lnb,
                                                     float* __restrict__ out)
{
    int n = blockIdx.x, c = threadIdx.x;
    float v = clip5(g_q[(size_t)n * DD + c]);
    float s = v, s2 = v * v;
#pragma unroll
    for (int o = 16; o; o >>= 1) {
        s  += __shfl_xor_sync(0xffffffffu, s, o);
        s2 += __shfl_xor_sync(0xffffffffu, s2, o);
    }
    __shared__ float sh[4], sh2[4];
    int w = c >> 5, l = c & 31;
    if (l == 0) { sh[w] = s; sh2[w] = s2; }
    __syncthreads();
    float S  = sh[0] + sh[1] + sh[2] + sh[3];
    float S2 = sh2[0] + sh2[1] + sh2[2] + sh2[3];
    float mean = S * (1.0f / 128.0f);
    float var  = S2 * (1.0f / 128.0f) - mean * mean;
    float y = (v - mean) * rsqrtf(var + 1e-5f) * lng[c] + lnb[c];
    out[(size_t)n * DD + c] = tanhf(y);
}

// ---------------- final mu_node gather + pos_attr (fused) ----------------
__global__ __launch_bounds__(128) void pos_gather(const float* __restrict__ mu,
                                                  const float* __restrict__ mpw,
                                                  float* __restrict__ out)
{
    int n = blockIdx.x, c = threadIdx.x;
    int s = g_rowptr[n], t = g_rowptr[n + 1];
    float s0 = 0.f, s1 = 0.f, s2 = 0.f;
    for (int k = s; k < t; k++) {
        int j = __ldg(&g_src[k]);
        const float* muj = mu + (size_t)j * DD3;
        s0 += muj[c];
        s1 += muj[DD + c];
        s2 += muj[2 * DD + c];
    }
    float w = mpw[c];
    s0 = clip5(s0) * w;
    s1 = clip5(s1) * w;
    s2 = clip5(s2) * w;
#pragma unroll
    for (int o = 16; o; o >>= 1) {
        s0 += __shfl_xor_sync(0xffffffffu, s0, o);
        s1 += __shfl_xor_sync(0xffffffffu, s1, o);
        s2 += __shfl_xor_sync(0xffffffffu, s2, o);
    }
    __shared__ float sh[4][3];
    int wd = c >> 5, l = c & 31;
    if (l == 0) { sh[wd][0] = s0; sh[wd][1] = s1; sh[wd][2] = s2; }
    __syncthreads();
    if (c < 3) {
        float v = sh[0][c] + sh[1][c] + sh[2][c] + sh[3][c];
        out[(size_t)n * 3 + c] = clip5(v);
    }
}

// ---------------- launch ----------------
extern "C" void kernel_launch(void* const* d_in, const int* in_sizes, int n_in,
                              void* d_out, int out_size)
{
    const float* z      = (const float*)d_in[0];
    const float* pos    = (const float*)d_in[1];
    const int*   ei     = (const int*)  d_in[2];
    const float* in_w   = (const float*)d_in[3];
    const float* in_b   = (const float*)d_in[4];
    const float* filt_w = (const float*)d_in[5];
    const float* filt_b = (const float*)d_in[6];
    const float* iw1    = (const float*)d_in[7];
    const float* ib1    = (const float*)d_in[8];
    const float* iw2    = (const float*)d_in[9];
    const float* ib2    = (const float*)d_in[10];
    const float* mmw    = (const float*)d_in[11];
    const float* mw1    = (const float*)d_in[12];
    const float* mb1    = (const float*)d_in[13];
    const float* mw2    = (const float*)d_in[14];
    const float* mb2    = (const float*)d_in[15];
    const float* mpw    = (const float*)d_in[16];
    const float* lng    = (const float*)d_in[17];
    const float* lnb    = (const float*)d_in[18];
    float* out = (float*)d_out;

    float *p_q, *p_h, *p_x, *p_mu, *p_mu2, *p_mumix, *p_ctx, *p_xm;
    cudaGetSymbolAddress((void**)&p_q,     g_q);
    cudaGetSymbolAddress((void**)&p_h,     g_h);
    cudaGetSymbolAddress((void**)&p_x,     g_x);
    cudaGetSymbolAddress((void**)&p_mu,    g_mu);
    cudaGetSymbolAddress((void**)&p_mu2,   g_mu2);
    cudaGetSymbolAddress((void**)&p_mumix, g_mumix);
    cudaGetSymbolAddress((void**)&p_ctx,   g_ctx);
    cudaGetSymbolAddress((void**)&p_xm,    g_xm);

    int gy_n  = (NN + 127) / 128;        // 157
    int gy_3n = (3 * NN + 127) / 128;    // 469

    init_bufs<<<(NN + 255) / 256, 256>>>();
    csr_count<<<(NE + 255) / 256, 256>>>(ei);
    csr_scan<<<1, 1024>>>();
    csr_fill<<<(NE + 255) / 256, 256>>>(ei);

    tgemm<1><<<dim3(1, gy_n), 256>>>(z, in_w, in_b, p_q, NN, 64, DD);
    edge_pre<<<(NE + 7) / 8, 256>>>(pos, ei, filt_w, filt_b);

    float* mu_in = p_mu;
    float* mu_out = p_mu2;
    for (int l = 0; l < LNUM; l++) {
        tgemm<1><<<dim3(1, gy_n), 256>>>(p_q, iw1 + (size_t)l * DD * DD, ib1 + (size_t)l * DD,
                                         p_h, NN, DD, DD);
        tgemm<0><<<dim3(3, gy_n), 256>>>(p_h, iw2 + (size_t)l * DD * DD3, ib2 + (size_t)l * DD3,
                                         p_x, NN, DD, DD3);
        if (l == 0)
            gather_msg<true><<<NN, 128>>>(mu_in, mu_out);
        else
            gather_msg<false><<<NN, 128>>>(mu_in, mu_out);
        tgemm<0><<<dim3(2, gy_3n), 256>>>(mu_out, mmw + (size_t)l * DD * 256, nullptr,
                                          p_mumix, 3 * NN, DD, 256);
        reduce_mix<<<NN, 128>>>();
        tgemm<1><<<dim3(1, gy_n), 256>>>(p_ctx, mw1 + (size_t)l * 256 * DD, mb1 + (size_t)l * DD,
                                         p_h, NN, 256, DD);
        tgemm<0><<<dim3(3, gy_n), 256>>>(p_h, mw2 + (size_t)l * DD * DD3, mb2 + (size_t)l * DD3,
                                         p_xm, NN, DD, DD3);
        update_node<<<NN, 128>>>(mu_out);
        float* tmp = mu_in; mu_in = mu_out; mu_out = tmp;
    }

    layernorm_out<<<NN, 128>>>(lng, lnb, out);
    pos_gather<<<NN, 128>>>(mu_in, mpw, out + (size_t)NN * DD);
}

// round 8
// speedup vs baseline: 1.1929x; 1.1099x over previous
#include <cuda_runtime.h>
#include <cuda_fp16.h>
#include <math.h>

#define NN 20000
#define NE 320000
#define DD 128
#define DD3 384
#define LNUM 3

// ---------------- scratch (static device globals) ----------------
__device__ __half g_filters[(size_t)NE * DD3];  // CSR-permuted, fp16, streaming
__device__ float g_dir[(size_t)NE * 4];         // CSR-permuted
__device__ int   g_src[NE];                      // CSR-permuted source node j
__device__ int   g_slot[NE];                     // edge id -> CSR slot
__device__ float g_q[(size_t)NN * DD];
__device__ float g_h[(size_t)NN * DD];
__device__ __half g_x[(size_t)NN * DD3];        // fp16 message features
__device__ float g_mu[(size_t)NN * DD3];
__device__ float g_mu2[(size_t)NN * DD3];
__device__ float g_mumix[(size_t)NN * 768];
__device__ float g_ctx[(size_t)NN * 256];
__device__ float g_dot[(size_t)NN * DD];
__device__ float g_xm[(size_t)NN * DD3];
__device__ int g_cnt[NN];
__device__ int g_rowptr[NN + 1];

__device__ __forceinline__ float siluf(float x) { return x / (1.0f + expf(-x)); }
__device__ __forceinline__ float clip5(float x) { return fminf(fmaxf(x, -5.0f), 5.0f); }

__device__ __forceinline__ unsigned f2tf32(float f)
{
    unsigned r;
    asm("cvt.rna.tf32.f32 %0, %1;" : "=r"(r) : "f"(f));
    return r;
}

__device__ __forceinline__ void mma_tf32(float* c, const unsigned* a, const unsigned* b)
{
    asm volatile(
        "mma.sync.aligned.m16n8k8.row.col.f32.tf32.tf32.f32 "
        "{%0,%1,%2,%3}, {%4,%5,%6,%7}, {%8,%9}, {%0,%1,%2,%3};"
        : "+f"(c[0]), "+f"(c[1]), "+f"(c[2]), "+f"(c[3])
        : "r"(a[0]), "r"(a[1]), "r"(a[2]), "r"(a[3]), "r"(b[0]), "r"(b[1]));
}

// ---------------- TF32 tensor-core GEMM: C = act(A[M,K] @ B[K,Nc] + bias) ----------------
// BM=128, BN=128, BK=16. 256 threads = 8 warps in 2(M)x4(N); warp tile 64x32.
// K % 16 == 0, Nc % 128 == 0.  (Round-4 proven version; OUTH writes fp16.)
#define AS_STRIDE 20
#define BS_STRIDE 136
template<int ACT, bool OUTH>
__global__ __launch_bounds__(256) void tgemm(const float* __restrict__ A,
                                             const float* __restrict__ B,
                                             const float* __restrict__ bias,
                                             float* __restrict__ C,
                                             int M, int K, int Nc)
{
    __shared__ float As[2][128][AS_STRIDE];
    __shared__ float Bs[2][16][BS_STRIDE];
    int tid = threadIdx.x;
    int wid = tid >> 5, lane = tid & 31;
    int g = lane >> 2, tg = lane & 3;
    int wm = wid & 1, wn = wid >> 1;
    int row0 = blockIdx.y * 128, col0 = blockIdx.x * 128;

    int arow = tid >> 1, acol = (tid & 1) * 8;
    int brow = tid >> 4, bcol = (tid & 15) * 8;
    bool aval = (row0 + arow) < M;
    const float* Aptr = A + (size_t)(row0 + arow) * K + acol;
    const float* Bptr = B + (size_t)brow * Nc + col0 + bcol;

    float acc[4][4][4];
#pragma unroll
    for (int mt = 0; mt < 4; mt++)
#pragma unroll
        for (int nt = 0; nt < 4; nt++)
#pragma unroll
            for (int r = 0; r < 4; r++) acc[mt][nt][r] = 0.0f;

    // prologue: tile 0 -> buffer 0
    float4 a0 = make_float4(0.f, 0.f, 0.f, 0.f), a1 = a0;
    if (aval) { a0 = *(const float4*)(Aptr); a1 = *(const float4*)(Aptr + 4); }
    float4 b0 = *(const float4*)(Bptr);
    float4 b1 = *(const float4*)(Bptr + 4);
    *(float4*)(&As[0][arow][acol])     = a0;
    *(float4*)(&As[0][arow][acol + 4]) = a1;
    *(float4*)(&Bs[0][brow][bcol])     = b0;
    *(float4*)(&Bs[0][brow][bcol + 4]) = b1;
    __syncthreads();

    int nt_tiles = K >> 4;
    for (int t = 0; t < nt_tiles; t++) {
        int cur = t & 1, nxt = cur ^ 1;
        float4 na0, na1, nb0, nb1;
        if (t + 1 < nt_tiles) {
            if (aval) {
                na0 = *(const float4*)(Aptr + (t + 1) * 16);
                na1 = *(const float4*)(Aptr + (t + 1) * 16 + 4);
            } else { na0 = make_float4(0.f,0.f,0.f,0.f); na1 = na0; }
            const float* bp = Bptr + (size_t)(t + 1) * 16 * Nc;
            nb0 = *(const float4*)(bp);
            nb1 = *(const float4*)(bp + 4);
        }
#pragma unroll
        for (int kc = 0; kc < 16; kc += 8) {
            unsigned ar[4][4], br[4][2];
#pragma unroll
            for (int mt = 0; mt < 4; mt++) {
                int r = wm * 64 + mt * 16;
                ar[mt][0] = f2tf32(As[cur][r + g][kc + tg]);
                ar[mt][1] = f2tf32(As[cur][r + g + 8][kc + tg]);
                ar[mt][2] = f2tf32(As[cur][r + g][kc + tg + 4]);
                ar[mt][3] = f2tf32(As[cur][r + g + 8][kc + tg + 4]);
            }
#pragma unroll
            for (int nt = 0; nt < 4; nt++) {
                int nc0 = wn * 32 + nt * 8;
                br[nt][0] = f2tf32(Bs[cur][kc + tg][nc0 + g]);
                br[nt][1] = f2tf32(Bs[cur][kc + tg + 4][nc0 + g]);
            }
#pragma unroll
            for (int mt = 0; mt < 4; mt++)
#pragma unroll
                for (int nt = 0; nt < 4; nt++)
                    mma_tf32(acc[mt][nt], ar[mt], br[nt]);
        }
        if (t + 1 < nt_tiles) {
            *(float4*)(&As[nxt][arow][acol])     = na0;
            *(float4*)(&As[nxt][arow][acol + 4]) = na1;
            *(float4*)(&Bs[nxt][brow][bcol])     = nb0;
            *(float4*)(&Bs[nxt][brow][bcol + 4]) = nb1;
        }
        __syncthreads();
    }

    // epilogue
#pragma unroll
    for (int mt = 0; mt < 4; mt++) {
#pragma unroll
        for (int nt = 0; nt < 4; nt++) {
            int col = col0 + wn * 32 + nt * 8 + 2 * tg;
            float bb0 = 0.f, bb1 = 0.f;
            if (bias) { bb0 = bias[col]; bb1 = bias[col + 1]; }
#pragma unroll
            for (int half = 0; half < 2; half++) {
                int row = row0 + wm * 64 + mt * 16 + g + half * 8;
                if (row >= M) continue;
                float v0 = acc[mt][nt][half * 2 + 0] + bb0;
                float v1 = acc[mt][nt][half * 2 + 1] + bb1;
                if (ACT == 1) { v0 = siluf(v0); v1 = siluf(v1); }
                if (OUTH) {
                    __half2* o = (__half2*)((__half*)C + (size_t)row * Nc + col);
                    *o = __floats2half2_rn(v0, v1);
                } else {
                    *(float2*)(C + (size_t)row * Nc + col) = make_float2(v0, v1);
                }
            }
        }
    }
}

// ---------------- CSR build ----------------
__global__ void init_bufs()
{
    int idx = blockIdx.x * blockDim.x + threadIdx.x;
    if (idx < NN) g_cnt[idx] = 0;
}

__global__ void csr_count(const int* __restrict__ ei)
{
    int e = blockIdx.x * blockDim.x + threadIdx.x;
    if (e < NE) atomicAdd(&g_cnt[ei[e]], 1);
}

__global__ __launch_bounds__(1024) void csr_scan()
{
    __shared__ int part[1024];
    int t = threadIdx.x;
    const int CH = (NN + 1023) / 1024;
    int base = t * CH;
    int s = 0;
    for (int k = 0; k < CH; k++) {
        int n = base + k;
        if (n < NN) s += g_cnt[n];
    }
    part[t] = s;
    __syncthreads();
    for (int off = 1; off < 1024; off <<= 1) {
        int v = (t >= off) ? part[t - off] : 0;
        __syncthreads();
        part[t] += v;
        __syncthreads();
    }
    int run = (t == 0) ? 0 : part[t - 1];
    for (int k = 0; k < CH; k++) {
        int n = base + k;
        if (n < NN) {
            g_rowptr[n] = run;
            run += g_cnt[n];
            g_cnt[n] = 0;
        }
    }
    if (t == 1023) g_rowptr[NN] = run;
}

__global__ void csr_fill(const int* __restrict__ ei)
{
    int e = blockIdx.x * blockDim.x + threadIdx.x;
    if (e < NE) {
        int i = ei[e];
        int pos = atomicAdd(&g_cnt[i], 1);
        int slot = g_rowptr[i] + pos;
        g_slot[e] = slot;
        g_src[slot] = ei[NE + e];
    }
}

// ---------------- per-edge geometry + RBF filters (fp16, streaming stores) ----------------
__global__ __launch_bounds__(256) void edge_pre(const float* __restrict__ pos,
                                                const int* __restrict__ ei,
                                                const float* __restrict__ fw,
                                                const float* __restrict__ fb)
{
    int e = blockIdx.x * 8 + (threadIdx.x >> 5);
    if (e >= NE) return;
    int lane = threadIdx.x & 31;
    int i = ei[e], j = ei[NE + e];
    int slot = g_slot[e];
    float rx = pos[j * 3 + 0] - pos[i * 3 + 0];
    float ry = pos[j * 3 + 1] - pos[i * 3 + 1];
    float rz = pos[j * 3 + 2] - pos[i * 3 + 2];
    float d = sqrtf(rx * rx + ry * ry + rz * rz);
    d = fmaxf(d, 1e-8f);
    float dv = (lane == 0) ? rx : ((lane == 1) ? ry : rz);
    if (lane < 3) g_dir[(size_t)slot * 4 + lane] = dv / d;
    if (lane == 3) g_dir[(size_t)slot * 4 + 3] = 0.f;

    const float spacing = 5.0f / 63.0f;
    const float coeff = -0.5f / (spacing * spacing);
    float xc = fminf(d * 0.2f, 1.0f);
    float fcut = (xc < 1.0f) ? 0.5f * (cospif(xc) + 1.0f) : 0.0f;

    float4 acc0 = make_float4(0.f, 0.f, 0.f, 0.f), acc1 = acc0, acc2 = acc0;
    if (fcut > 0.0f) {
        int k0 = (int)rintf(d / spacing);
        int lo = max(0, k0 - 8), hi = min(63, k0 + 8);
        const float4* fw4 = (const float4*)fw;
        for (int k = lo; k <= hi; k++) {
            float t = d - (float)k * spacing;
            float p = expf(coeff * t * t);
            float4 w0 = fw4[k * 96 + lane];
            float4 w1 = fw4[k * 96 + lane + 32];
            float4 w2 = fw4[k * 96 + lane + 64];
            acc0.x += p * w0.x; acc0.y += p * w0.y; acc0.z += p * w0.z; acc0.w += p * w0.w;
            acc1.x += p * w1.x; acc1.y += p * w1.y; acc1.z += p * w1.z; acc1.w += p * w1.w;
            acc2.x += p * w2.x; acc2.y += p * w2.y; acc2.z += p * w2.z; acc2.w += p * w2.w;
        }
    }
    const float4* fb4 = (const float4*)fb;
    __half2* outh = (__half2*)(g_filters + (size_t)slot * DD3);
#pragma unroll
    for (int grp = 0; grp < 3; grp++) {
        float4 a = (grp == 0) ? acc0 : ((grp == 1) ? acc1 : acc2);
        float4 b = fb4[lane + 32 * grp];
        float v0 = clip5((a.x + b.x) * fcut);
        float v1 = clip5((a.y + b.y) * fcut);
        float v2 = clip5((a.z + b.z) * fcut);
        float v3 = clip5((a.w + b.w) * fcut);
        int base2 = (grp * 128 + lane * 4) >> 1;
        __stcs(outh + base2,     __floats2half2_rn(v0, v1));
        __stcs(outh + base2 + 1, __floats2half2_rn(v2, v3));
    }
}

// ---------------- CSR gather of edge messages (half2-vectorized) ----------------
// 2 nodes per block; 64 threads per node; each thread owns 2 channels (one half2/float2).
template<bool MUZERO>
__global__ __launch_bounds__(128) void gather_msg(const float* __restrict__ mu_in,
                                                  float* __restrict__ mu_out)
{
    int n = blockIdx.x * 2 + (threadIdx.x >> 6);
    int c2 = threadIdx.x & 63;           // half2/float2 channel index
    int s = g_rowptr[n], t = g_rowptr[n + 1];
    float2 aq = make_float2(0.f, 0.f);
    float2 m0 = aq, m1 = aq, m2 = aq;
    for (int k = s; k < t; k++) {
        int j = __ldg(&g_src[k]);
        const __half2* f  = (const __half2*)(g_filters + (size_t)k * DD3);
        const __half2* xj = (const __half2*)(g_x + (size_t)j * DD3);
        float2 fq = __half22float2(__ldcs(f + c2));
        float2 fR = __half22float2(__ldcs(f + 64 + c2));
        float2 fm = __half22float2(__ldcs(f + 128 + c2));
        float2 xq = __half22float2(xj[c2]);
        float2 xR = __half22float2(xj[64 + c2]);
        float2 xm = __half22float2(xj[128 + c2]);
        float4 dv = __ldcs((const float4*)(g_dir + (size_t)k * 4));
        float2 dmuR = make_float2(xR.x * fR.x, xR.y * fR.y);
        aq.x += xq.x * fq.x;
        aq.y += xq.y * fq.y;
        if (MUZERO) {
            m0.x += dmuR.x * dv.x; m0.y += dmuR.y * dv.x;
            m1.x += dmuR.x * dv.y; m1.y += dmuR.y * dv.y;
            m2.x += dmuR.x * dv.z; m2.y += dmuR.y * dv.z;
        } else {
            float2 dmm = make_float2(xm.x * fm.x, xm.y * fm.y);
            const float2* muj = (const float2*)(mu_in + (size_t)j * DD3);
            float2 u0 = muj[c2], u1 = muj[64 + c2], u2 = muj[128 + c2];
            m0.x += dmuR.x * dv.x + dmm.x * u0.x; m0.y += dmuR.y * dv.x + dmm.y * u0.y;
            m1.x += dmuR.x * dv.y + dmm.x * u1.x; m1.y += dmuR.y * dv.y + dmm.y * u1.y;
            m2.x += dmuR.x * dv.z + dmm.x * u2.x; m2.y += dmuR.y * dv.z + dmm.y * u2.y;
        }
    }
    float2* qp = (float2*)(g_q + (size_t)n * DD);
    float2 qv = qp[c2];
    qv.x += aq.x; qv.y += aq.y;
    qp[c2] = qv;
    float2* muo = (float2*)(mu_out + (size_t)n * DD3);
    if (MUZERO) {
        muo[c2]       = m0;
        muo[64 + c2]  = m1;
        muo[128 + c2] = m2;
    } else {
        const float2* mui = (const float2*)(mu_in + (size_t)n * DD3);
        float2 u0 = mui[c2], u1 = mui[64 + c2], u2 = mui[128 + c2];
        u0.x += m0.x; u0.y += m0.y;
        u1.x += m1.x; u1.y += m1.y;
        u2.x += m2.x; u2.y += m2.y;
        muo[c2]       = u0;
        muo[64 + c2]  = u1;
        muo[128 + c2] = u2;
    }
}

// ---------------- mu_Vn / dot(mu_V,mu_W) / ctx ----------------
__global__ __launch_bounds__(128) void reduce_mix()
{
    int n = blockIdx.x, c = threadIdx.x;
    size_t base = (size_t)n * 768;
    float v0 = g_mumix[base + c],        w0 = g_mumix[base + 128 + c];
    float v1 = g_mumix[base + 256 + c],  w1 = g_mumix[base + 384 + c];
    float v2 = g_mumix[base + 512 + c],  w2 = g_mumix[base + 640 + c];
    float vn = sqrtf(v0 * v0 + v1 * v1 + v2 * v2 + 1e-8f);
    g_ctx[(size_t)n * 256 + c]       = g_q[(size_t)n * DD + c];
    g_ctx[(size_t)n * 256 + 128 + c] = vn;
    g_dot[(size_t)n * DD + c] = v0 * w0 + v1 * w1 + v2 * w2;
}

// ---------------- q,mu self-update ----------------
__global__ __launch_bounds__(128) void update_node(float* __restrict__ mu)
{
    int n = blockIdx.x, c = threadIdx.x;
    size_t xb = (size_t)n * DD3;
    float dq_i  = g_xm[xb + c];
    float dmu_i = g_xm[xb + DD + c];
    float dqmu  = g_xm[xb + 2 * DD + c];
    g_q[(size_t)n * DD + c] += dq_i + dqmu * g_dot[(size_t)n * DD + c];
    size_t mb = (size_t)n * 768;
#pragma unroll
    for (int a = 0; a < 3; a++)
        mu[(size_t)n * DD3 + a * DD + c] += dmu_i * g_mumix[mb + a * 256 + 128 + c];
}

// ---------------- final layernorm -> tanh ----------------
__global__ __launch_bounds__(128) void layernorm_out(const float* __restrict__ lng,
                                                     const float* __restrict__ lnb,
                                                     float* __restrict__ out)
{
    int n = blockIdx.x, c = threadIdx.x;
    float v = clip5(g_q[(size_t)n * DD + c]);
    float s = v, s2 = v * v;
#pragma unroll
    for (int o = 16; o; o >>= 1) {
        s  += __shfl_xor_sync(0xffffffffu, s, o);
        s2 += __shfl_xor_sync(0xffffffffu, s2, o);
    }
    __shared__ float sh[4], sh2[4];
    int w = c >> 5, l = c & 31;
    if (l == 0) { sh[w] = s; sh2[w] = s2; }
    __syncthreads();
    float S  = sh[0] + sh[1] + sh[2] + sh[3];
    float S2 = sh2[0] + sh2[1] + sh2[2] + sh2[3];
    float mean = S * (1.0f / 128.0f);
    float var  = S2 * (1.0f / 128.0f) - mean * mean;
    float y = (v - mean) * rsqrtf(var + 1e-5f) * lng[c] + lnb[c];
    out[(size_t)n * DD + c] = tanhf(y);
}

// ---------------- final mu_node gather + pos_attr (fused) ----------------
__global__ __launch_bounds__(128) void pos_gather(const float* __restrict__ mu,
                                                  const float* __restrict__ mpw,
                                                  float* __restrict__ out)
{
    int n = blockIdx.x, c = threadIdx.x;
    int s = g_rowptr[n], t = g_rowptr[n + 1];
    float s0 = 0.f, s1 = 0.f, s2 = 0.f;
    for (int k = s; k < t; k++) {
        int j = __ldg(&g_src[k]);
        const float* muj = mu + (size_t)j * DD3;
        s0 += muj[c];
        s1 += muj[DD + c];
        s2 += muj[2 * DD + c];
    }
    float w = mpw[c];
    s0 = clip5(s0) * w;
    s1 = clip5(s1) * w;
    s2 = clip5(s2) * w;
#pragma unroll
    for (int o = 16; o; o >>= 1) {
        s0 += __shfl_xor_sync(0xffffffffu, s0, o);
        s1 += __shfl_xor_sync(0xffffffffu, s1, o);
        s2 += __shfl_xor_sync(0xffffffffu, s2, o);
    }
    __shared__ float sh[4][3];
    int wd = c >> 5, l = c & 31;
    if (l == 0) { sh[wd][0] = s0; sh[wd][1] = s1; sh[wd][2] = s2; }
    __syncthreads();
    if (c < 3) {
        float v = sh[0][c] + sh[1][c] + sh[2][c] + sh[3][c];
        out[(size_t)n * 3 + c] = clip5(v);
    }
}

// ---------------- launch ----------------
extern "C" void kernel_launch(void* const* d_in, const int* in_sizes, int n_in,
                              void* d_out, int out_size)
{
    const float* z      = (const float*)d_in[0];
    const float* pos    = (const float*)d_in[1];
    const int*   ei     = (const int*)  d_in[2];
    const float* in_w   = (const float*)d_in[3];
    const float* in_b   = (const float*)d_in[4];
    const float* filt_w = (const float*)d_in[5];
    const float* filt_b = (const float*)d_in[6];
    const float* iw1    = (const float*)d_in[7];
    const float* ib1    = (const float*)d_in[8];
    const float* iw2    = (const float*)d_in[9];
    const float* ib2    = (const float*)d_in[10];
    const float* mmw    = (const float*)d_in[11];
    const float* mw1    = (const float*)d_in[12];
    const float* mb1    = (const float*)d_in[13];
    const float* mw2    = (const float*)d_in[14];
    const float* mb2    = (const float*)d_in[15];
    const float* mpw    = (const float*)d_in[16];
    const float* lng    = (const float*)d_in[17];
    const float* lnb    = (const float*)d_in[18];
    float* out = (float*)d_out;

    float *p_q, *p_h, *p_mu, *p_mu2, *p_mumix, *p_ctx, *p_xm;
    __half* p_x;
    cudaGetSymbolAddress((void**)&p_q,     g_q);
    cudaGetSymbolAddress((void**)&p_h,     g_h);
    cudaGetSymbolAddress((void**)&p_x,     g_x);
    cudaGetSymbolAddress((void**)&p_mu,    g_mu);
    cudaGetSymbolAddress((void**)&p_mu2,   g_mu2);
    cudaGetSymbolAddress((void**)&p_mumix, g_mumix);
    cudaGetSymbolAddress((void**)&p_ctx,   g_ctx);
    cudaGetSymbolAddress((void**)&p_xm,    g_xm);

    int gy_n  = (NN + 127) / 128;        // 157
    int gy_3n = (3 * NN + 127) / 128;    // 469

    init_bufs<<<(NN + 255) / 256, 256>>>();
    csr_count<<<(NE + 255) / 256, 256>>>(ei);
    csr_scan<<<1, 1024>>>();
    csr_fill<<<(NE + 255) / 256, 256>>>(ei);

    tgemm<1,false><<<dim3(1, gy_n), 256>>>(z, in_w, in_b, p_q, NN, 64, DD);
    edge_pre<<<(NE + 7) / 8, 256>>>(pos, ei, filt_w, filt_b);

    float* mu_in = p_mu;
    float* mu_out = p_mu2;
    for (int l = 0; l < LNUM; l++) {
        tgemm<1,false><<<dim3(1, gy_n), 256>>>(p_q, iw1 + (size_t)l * DD * DD, ib1 + (size_t)l * DD,
                                               p_h, NN, DD, DD);
        tgemm<0,true><<<dim3(3, gy_n), 256>>>(p_h, iw2 + (size_t)l * DD * DD3, ib2 + (size_t)l * DD3,
                                              (float*)p_x, NN, DD, DD3);
        if (l == 0)
            gather_msg<true><<<NN / 2, 128>>>(mu_in, mu_out);
        else
            gather_msg<false><<<NN / 2, 128>>>(mu_in, mu_out);
        tgemm<0,false><<<dim3(2, gy_3n), 256>>>(mu_out, mmw + (size_t)l * DD * 256, nullptr,
                                                p_mumix, 3 * NN, DD, 256);
        reduce_mix<<<NN, 128>>>();
        tgemm<1,false><<<dim3(1, gy_n), 256>>>(p_ctx, mw1 + (size_t)l * 256 * DD, mb1 + (size_t)l * DD,
                                               p_h, NN, 256, DD);
        tgemm<0,false><<<dim3(3, gy_n), 256>>>(p_h, mw2 + (size_t)l * DD * DD3, mb2 + (size_t)l * DD3,
                                               p_xm, NN, DD, DD3);
        update_node<<<NN, 128>>>(mu_out);
        float* tmp = mu_in; mu_in = mu_out; mu_out = tmp;
    }

    layernorm_out<<<NN, 128>>>(lng, lnb, out);
    pos_gather<<<NN, 128>>>(mu_in, mpw, out + (size_t)NN * DD);
}

// round 12
// speedup vs baseline: 1.2796x; 1.0727x over previous
#include <cuda_runtime.h>
#include <cuda_fp16.h>
#include <math.h>

#define NN 20000
#define NE 320000
#define DD 128
#define DD3 384
#define LNUM 3

// ---------------- scratch (static device globals) ----------------
__device__ __half g_filters[(size_t)NE * DD3];  // CSR-permuted, fp16, streaming
__device__ float g_dir[(size_t)NE * 4];         // CSR-permuted
__device__ int   g_src[NE];                      // CSR-permuted source node j
__device__ int   g_slot[NE];                     // edge id -> CSR slot
__device__ float g_q[(size_t)NN * DD];
__device__ float g_h[(size_t)NN * DD];
__device__ __half g_x[(size_t)NN * DD3];        // fp16 message features
__device__ float g_mu[(size_t)NN * DD3];
__device__ float g_mu2[(size_t)NN * DD3];
__device__ float g_mumix[(size_t)NN * 768];
__device__ float g_ctx[(size_t)NN * 256];
__device__ float g_dot[(size_t)NN * DD];
__device__ float g_xm[(size_t)NN * DD3];
__device__ int g_cnt[NN];
__device__ int g_rowptr[NN + 1];

__device__ __forceinline__ float siluf(float x) { return x / (1.0f + expf(-x)); }
__device__ __forceinline__ float clip5(float x) { return fminf(fmaxf(x, -5.0f), 5.0f); }

__device__ __forceinline__ void mma_f16(float* c, const unsigned* a, const unsigned* b)
{
    asm volatile(
        "mma.sync.aligned.m16n8k16.row.col.f32.f16.f16.f32 "
        "{%0,%1,%2,%3}, {%4,%5,%6,%7}, {%8,%9}, {%0,%1,%2,%3};"
        : "+f"(c[0]), "+f"(c[1]), "+f"(c[2]), "+f"(c[3])
        : "r"(a[0]), "r"(a[1]), "r"(a[2]), "r"(a[3]), "r"(b[0]), "r"(b[1]));
}

// ---------------- FP16 tensor-core GEMM: C = act(A[M,K] @ B[K,Nc] + bias) ----------------
// BM=128, BN=128, BK=16. 256 threads = 8 warps in 2(M)x4(N); warp tile 64x32.
// fp32 global loads, fp16 smem (k-pair-packed half2), fp32 accumulate.
// K % 16 == 0, Nc % 128 == 0.
#define HS2 140   // half2 stride: 140 ≡ 12 mod 32 -> conflict-free frag loads; 4*140 ≡ 16 -> conflict-free stores
template<int ACT, bool OUTH>
__global__ __launch_bounds__(256) void tgemm(const float* __restrict__ A,
                                             const float* __restrict__ B,
                                             const float* __restrict__ bias,
                                             float* __restrict__ C,
                                             int M, int K, int Nc)
{
    // As2[k2][m] = half2(A[m][2*k2], A[m][2*k2+1]); Bs2[k2][n] = half2(B[2*k2][n], B[2*k2+1][n])
    __shared__ __half2 As2[2][8][HS2];
    __shared__ __half2 Bs2[2][8][HS2];
    int tid = threadIdx.x;
    int wid = tid >> 5, lane = tid & 31;
    int g = lane >> 2, tg = lane & 3;
    int wm = wid & 1, wn = wid >> 1;
    int row0 = blockIdx.y * 128, col0 = blockIdx.x * 128;

    int arow = tid >> 1, ak2 = (tid & 1) * 4;        // A: 8 floats of one row
    int bk2 = tid >> 5, bcol = (tid & 31) * 4;       // B: 4 cols of a k-pair
    bool aval = (row0 + arow) < M;
    const float* Aptr = A + (size_t)(row0 + arow) * K + ak2 * 2;
    const float* Bp0 = B + (size_t)(2 * bk2) * Nc + col0 + bcol;
    const float* Bp1 = Bp0 + Nc;

    float acc[4][4][4];
#pragma unroll
    for (int mt = 0; mt < 4; mt++)
#pragma unroll
        for (int nt = 0; nt < 4; nt++)
#pragma unroll
            for (int r = 0; r < 4; r++) acc[mt][nt][r] = 0.0f;

    // prologue: tile 0 -> buffer 0
    {
        float4 a0 = make_float4(0.f, 0.f, 0.f, 0.f), a1 = a0;
        if (aval) { a0 = *(const float4*)(Aptr); a1 = *(const float4*)(Aptr + 4); }
        As2[0][ak2 + 0][arow] = __floats2half2_rn(a0.x, a0.y);
        As2[0][ak2 + 1][arow] = __floats2half2_rn(a0.z, a0.w);
        As2[0][ak2 + 2][arow] = __floats2half2_rn(a1.x, a1.y);
        As2[0][ak2 + 3][arow] = __floats2half2_rn(a1.z, a1.w);
        float4 b0 = *(const float4*)(Bp0);
        float4 b1 = *(const float4*)(Bp1);
        Bs2[0][bk2][bcol + 0] = __floats2half2_rn(b0.x, b1.x);
        Bs2[0][bk2][bcol + 1] = __floats2half2_rn(b0.y, b1.y);
        Bs2[0][bk2][bcol + 2] = __floats2half2_rn(b0.z, b1.z);
        Bs2[0][bk2][bcol + 3] = __floats2half2_rn(b0.w, b1.w);
    }
    __syncthreads();

    int ntl = K >> 4;
    for (int t = 0; t < ntl; t++) {
        int cur = t & 1, nxt = cur ^ 1;
        float4 na0, na1, nb0, nb1;
        if (t + 1 < ntl) {
            if (aval) {
                na0 = *(const float4*)(Aptr + (t + 1) * 16);
                na1 = *(const float4*)(Aptr + (t + 1) * 16 + 4);
            } else { na0 = make_float4(0.f,0.f,0.f,0.f); na1 = na0; }
            nb0 = *(const float4*)(Bp0 + (size_t)(t + 1) * 16 * Nc);
            nb1 = *(const float4*)(Bp1 + (size_t)(t + 1) * 16 * Nc);
        }
        // compute: one m16n8k16 group per warp tile cell
        unsigned ar[4][4], br[4][2];
#pragma unroll
        for (int mt = 0; mt < 4; mt++) {
            int r = wm * 64 + mt * 16 + g;
            ar[mt][0] = *(const unsigned*)&As2[cur][tg][r];
            ar[mt][1] = *(const unsigned*)&As2[cur][tg][r + 8];
            ar[mt][2] = *(const unsigned*)&As2[cur][tg + 4][r];
            ar[mt][3] = *(const unsigned*)&As2[cur][tg + 4][r + 8];
        }
#pragma unroll
        for (int nt = 0; nt < 4; nt++) {
            int n0 = wn * 32 + nt * 8 + g;
            br[nt][0] = *(const unsigned*)&Bs2[cur][tg][n0];
            br[nt][1] = *(const unsigned*)&Bs2[cur][tg + 4][n0];
        }
#pragma unroll
        for (int mt = 0; mt < 4; mt++)
#pragma unroll
            for (int nt = 0; nt < 4; nt++)
                mma_f16(acc[mt][nt], ar[mt], br[nt]);

        if (t + 1 < ntl) {
            As2[nxt][ak2 + 0][arow] = __floats2half2_rn(na0.x, na0.y);
            As2[nxt][ak2 + 1][arow] = __floats2half2_rn(na0.z, na0.w);
            As2[nxt][ak2 + 2][arow] = __floats2half2_rn(na1.x, na1.y);
            As2[nxt][ak2 + 3][arow] = __floats2half2_rn(na1.z, na1.w);
            Bs2[nxt][bk2][bcol + 0] = __floats2half2_rn(nb0.x, nb1.x);
            Bs2[nxt][bk2][bcol + 1] = __floats2half2_rn(nb0.y, nb1.y);
            Bs2[nxt][bk2][bcol + 2] = __floats2half2_rn(nb0.z, nb1.z);
            Bs2[nxt][bk2][bcol + 3] = __floats2half2_rn(nb0.w, nb1.w);
        }
        __syncthreads();
    }

    // epilogue
#pragma unroll
    for (int mt = 0; mt < 4; mt++) {
#pragma unroll
        for (int nt = 0; nt < 4; nt++) {
            int col = col0 + wn * 32 + nt * 8 + 2 * tg;
            float bb0 = 0.f, bb1 = 0.f;
            if (bias) { bb0 = bias[col]; bb1 = bias[col + 1]; }
#pragma unroll
            for (int half = 0; half < 2; half++) {
                int row = row0 + wm * 64 + mt * 16 + g + half * 8;
                if (row >= M) continue;
                float v0 = acc[mt][nt][half * 2 + 0] + bb0;
                float v1 = acc[mt][nt][half * 2 + 1] + bb1;
                if (ACT == 1) { v0 = siluf(v0); v1 = siluf(v1); }
                if (OUTH) {
                    __half2* o = (__half2*)((__half*)C + (size_t)row * Nc + col);
                    *o = __floats2half2_rn(v0, v1);
                } else {
                    *(float2*)(C + (size_t)row * Nc + col) = make_float2(v0, v1);
                }
            }
        }
    }
}

// ---------------- CSR build ----------------
__global__ void init_bufs()
{
    int idx = blockIdx.x * blockDim.x + threadIdx.x;
    if (idx < NN) g_cnt[idx] = 0;
}

__global__ void csr_count(const int* __restrict__ ei)
{
    int e = blockIdx.x * blockDim.x + threadIdx.x;
    if (e < NE) atomicAdd(&g_cnt[ei[e]], 1);
}

__global__ __launch_bounds__(1024) void csr_scan()
{
    __shared__ int part[1024];
    int t = threadIdx.x;
    const int CH = (NN + 1023) / 1024;
    int base = t * CH;
    int s = 0;
    for (int k = 0; k < CH; k++) {
        int n = base + k;
        if (n < NN) s += g_cnt[n];
    }
    part[t] = s;
    __syncthreads();
    for (int off = 1; off < 1024; off <<= 1) {
        int v = (t >= off) ? part[t - off] : 0;
        __syncthreads();
        part[t] += v;
        __syncthreads();
    }
    int run = (t == 0) ? 0 : part[t - 1];
    for (int k = 0; k < CH; k++) {
        int n = base + k;
        if (n < NN) {
            g_rowptr[n] = run;
            run += g_cnt[n];
            g_cnt[n] = 0;
        }
    }
    if (t == 1023) g_rowptr[NN] = run;
}

__global__ void csr_fill(const int* __restrict__ ei)
{
    int e = blockIdx.x * blockDim.x + threadIdx.x;
    if (e < NE) {
        int i = ei[e];
        int pos = atomicAdd(&g_cnt[i], 1);
        int slot = g_rowptr[i] + pos;
        g_slot[e] = slot;
        g_src[slot] = ei[NE + e];
    }
}

// ---------------- per-edge geometry + RBF filters (fp16, streaming stores) ----------------
__global__ __launch_bounds__(256) void edge_pre(const float* __restrict__ pos,
                                                const int* __restrict__ ei,
                                                const float* __restrict__ fw,
                                                const float* __restrict__ fb)
{
    int e = blockIdx.x * 8 + (threadIdx.x >> 5);
    if (e >= NE) return;
    int lane = threadIdx.x & 31;
    int i = ei[e], j = ei[NE + e];
    int slot = g_slot[e];
    float rx = pos[j * 3 + 0] - pos[i * 3 + 0];
    float ry = pos[j * 3 + 1] - pos[i * 3 + 1];
    float rz = pos[j * 3 + 2] - pos[i * 3 + 2];
    float d = sqrtf(rx * rx + ry * ry + rz * rz);
    d = fmaxf(d, 1e-8f);
    float dv = (lane == 0) ? rx : ((lane == 1) ? ry : rz);
    if (lane < 3) g_dir[(size_t)slot * 4 + lane] = dv / d;
    if (lane == 3) g_dir[(size_t)slot * 4 + 3] = 0.f;

    const float spacing = 5.0f / 63.0f;
    const float coeff = -0.5f / (spacing * spacing);
    float xc = fminf(d * 0.2f, 1.0f);
    float fcut = (xc < 1.0f) ? 0.5f * (cospif(xc) + 1.0f) : 0.0f;

    float4 acc0 = make_float4(0.f, 0.f, 0.f, 0.f), acc1 = acc0, acc2 = acc0;
    if (fcut > 0.0f) {
        int k0 = (int)rintf(d / spacing);
        int lo = max(0, k0 - 8), hi = min(63, k0 + 8);
        const float4* fw4 = (const float4*)fw;
        for (int k = lo; k <= hi; k++) {
            float t = d - (float)k * spacing;
            float p = expf(coeff * t * t);
            float4 w0 = fw4[k * 96 + lane];
            float4 w1 = fw4[k * 96 + lane + 32];
            float4 w2 = fw4[k * 96 + lane + 64];
            acc0.x += p * w0.x; acc0.y += p * w0.y; acc0.z += p * w0.z; acc0.w += p * w0.w;
            acc1.x += p * w1.x; acc1.y += p * w1.y; acc1.z += p * w1.z; acc1.w += p * w1.w;
            acc2.x += p * w2.x; acc2.y += p * w2.y; acc2.z += p * w2.z; acc2.w += p * w2.w;
        }
    }
    const float4* fb4 = (const float4*)fb;
    __half2* outh = (__half2*)(g_filters + (size_t)slot * DD3);
#pragma unroll
    for (int grp = 0; grp < 3; grp++) {
        float4 a = (grp == 0) ? acc0 : ((grp == 1) ? acc1 : acc2);
        float4 b = fb4[lane + 32 * grp];
        float v0 = clip5((a.x + b.x) * fcut);
        float v1 = clip5((a.y + b.y) * fcut);
        float v2 = clip5((a.z + b.z) * fcut);
        float v3 = clip5((a.w + b.w) * fcut);
        int base2 = (grp * 128 + lane * 4) >> 1;
        __stcs(outh + base2,     __floats2half2_rn(v0, v1));
        __stcs(outh + base2 + 1, __floats2half2_rn(v2, v3));
    }
}

// ---------------- CSR gather of edge messages (half2-vectorized) ----------------
// 2 nodes per block; 64 threads per node; each thread owns 2 channels (one half2/float2).
template<bool MUZERO>
__global__ __launch_bounds__(128) void gather_msg(const float* __restrict__ mu_in,
                                                  float* __restrict__ mu_out)
{
    int n = blockIdx.x * 2 + (threadIdx.x >> 6);
    int c2 = threadIdx.x & 63;           // half2/float2 channel index
    int s = g_rowptr[n], t = g_rowptr[n + 1];
    float2 aq = make_float2(0.f, 0.f);
    float2 m0 = aq, m1 = aq, m2 = aq;
    for (int k = s; k < t; k++) {
        int j = __ldg(&g_src[k]);
        const __half2* f  = (const __half2*)(g_filters + (size_t)k * DD3);
        const __half2* xj = (const __half2*)(g_x + (size_t)j * DD3);
        float2 fq = __half22float2(__ldcs(f + c2));
        float2 fR = __half22float2(__ldcs(f + 64 + c2));
        float2 fm = __half22float2(__ldcs(f + 128 + c2));
        float2 xq = __half22float2(xj[c2]);
        float2 xR = __half22float2(xj[64 + c2]);
        float2 xm = __half22float2(xj[128 + c2]);
        float4 dv = __ldcs((const float4*)(g_dir + (size_t)k * 4));
        float2 dmuR = make_float2(xR.x * fR.x, xR.y * fR.y);
        aq.x += xq.x * fq.x;
        aq.y += xq.y * fq.y;
        if (MUZERO) {
            m0.x += dmuR.x * dv.x; m0.y += dmuR.y * dv.x;
            m1.x += dmuR.x * dv.y; m1.y += dmuR.y * dv.y;
            m2.x += dmuR.x * dv.z; m2.y += dmuR.y * dv.z;
        } else {
            float2 dmm = make_float2(xm.x * fm.x, xm.y * fm.y);
            const float2* muj = (const float2*)(mu_in + (size_t)j * DD3);
            float2 u0 = muj[c2], u1 = muj[64 + c2], u2 = muj[128 + c2];
            m0.x += dmuR.x * dv.x + dmm.x * u0.x; m0.y += dmuR.y * dv.x + dmm.y * u0.y;
            m1.x += dmuR.x * dv.y + dmm.x * u1.x; m1.y += dmuR.y * dv.y + dmm.y * u1.y;
            m2.x += dmuR.x * dv.z + dmm.x * u2.x; m2.y += dmuR.y * dv.z + dmm.y * u2.y;
        }
    }
    float2* qp = (float2*)(g_q + (size_t)n * DD);
    float2 qv = qp[c2];
    qv.x += aq.x; qv.y += aq.y;
    qp[c2] = qv;
    float2* muo = (float2*)(mu_out + (size_t)n * DD3);
    if (MUZERO) {
        muo[c2]       = m0;
        muo[64 + c2]  = m1;
        muo[128 + c2] = m2;
    } else {
        const float2* mui = (const float2*)(mu_in + (size_t)n * DD3);
        float2 u0 = mui[c2], u1 = mui[64 + c2], u2 = mui[128 + c2];
        u0.x += m0.x; u0.y += m0.y;
        u1.x += m1.x; u1.y += m1.y;
        u2.x += m2.x; u2.y += m2.y;
        muo[c2]       = u0;
        muo[64 + c2]  = u1;
        muo[128 + c2] = u2;
    }
}

// ---------------- mu_Vn / dot(mu_V,mu_W) / ctx ----------------
__global__ __launch_bounds__(128) void reduce_mix()
{
    int n = blockIdx.x, c = threadIdx.x;
    size_t base = (size_t)n * 768;
    float v0 = g_mumix[base + c],        w0 = g_mumix[base + 128 + c];
    float v1 = g_mumix[base + 256 + c],  w1 = g_mumix[base + 384 + c];
    float v2 = g_mumix[base + 512 + c],  w2 = g_mumix[base + 640 + c];
    float vn = sqrtf(v0 * v0 + v1 * v1 + v2 * v2 + 1e-8f);
    g_ctx[(size_t)n * 256 + c]       = g_q[(size_t)n * DD + c];
    g_ctx[(size_t)n * 256 + 128 + c] = vn;
    g_dot[(size_t)n * DD + c] = v0 * w0 + v1 * w1 + v2 * w2;
}

// ---------------- q,mu self-update ----------------
__global__ __launch_bounds__(128) void update_node(float* __restrict__ mu)
{
    int n = blockIdx.x, c = threadIdx.x;
    size_t xb = (size_t)n * DD3;
    float dq_i  = g_xm[xb + c];
    float dmu_i = g_xm[xb + DD + c];
    float dqmu  = g_xm[xb + 2 * DD + c];
    g_q[(size_t)n * DD + c] += dq_i + dqmu * g_dot[(size_t)n * DD + c];
    size_t mb = (size_t)n * 768;
#pragma unroll
    for (int a = 0; a < 3; a++)
        mu[(size_t)n * DD3 + a * DD + c] += dmu_i * g_mumix[mb + a * 256 + 128 + c];
}

// ---------------- final layernorm -> tanh ----------------
__global__ __launch_bounds__(128) void layernorm_out(const float* __restrict__ lng,
                                                     const float* __restrict__ lnb,
                                                     float* __restrict__ out)
{
    int n = blockIdx.x, c = threadIdx.x;
    float v = clip5(g_q[(size_t)n * DD + c]);
    float s = v, s2 = v * v;
#pragma unroll
    for (int o = 16; o; o >>= 1) {
        s  += __shfl_xor_sync(0xffffffffu, s, o);
        s2 += __shfl_xor_sync(0xffffffffu, s2, o);
    }
    __shared__ float sh[4], sh2[4];
    int w = c >> 5, l = c & 31;
    if (l == 0) { sh[w] = s; sh2[w] = s2; }
    __syncthreads();
    float sumv  = sh[0] + sh[1] + sh[2] + sh[3];
    float sumsq = sh2[0] + sh2[1] + sh2[2] + sh2[3];
    float mean = sumv * (1.0f / 128.0f);
    float var  = sumsq * (1.0f / 128.0f) - mean * mean;
    float y = (v - mean) * rsqrtf(var + 1e-5f) * lng[c] + lnb[c];
    out[(size_t)n * DD + c] = tanhf(y);
}

// ---------------- final mu_node gather + pos_attr (fused) ----------------
__global__ __launch_bounds__(128) void pos_gather(const float* __restrict__ mu,
                                                  const float* __restrict__ mpw,
                                                  float* __restrict__ out)
{
    int n = blockIdx.x, c = threadIdx.x;
    int s = g_rowptr[n], t = g_rowptr[n + 1];
    float s0 = 0.f, s1 = 0.f, s2v = 0.f;
    for (int k = s; k < t; k++) {
        int j = __ldg(&g_src[k]);
        const float* muj = mu + (size_t)j * DD3;
        s0  += muj[c];
        s1  += muj[DD + c];
        s2v += muj[2 * DD + c];
    }
    float w = mpw[c];
    s0  = clip5(s0) * w;
    s1  = clip5(s1) * w;
    s2v = clip5(s2v) * w;
#pragma unroll
    for (int o = 16; o; o >>= 1) {
        s0  += __shfl_xor_sync(0xffffffffu, s0, o);
        s1  += __shfl_xor_sync(0xffffffffu, s1, o);
        s2v += __shfl_xor_sync(0xffffffffu, s2v, o);
    }
    __shared__ float sh[4][3];
    int wd = c >> 5, l = c & 31;
    if (l == 0) { sh[wd][0] = s0; sh[wd][1] = s1; sh[wd][2] = s2v; }
    __syncthreads();
    if (c < 3) {
        float v = sh[0][c] + sh[1][c] + sh[2][c] + sh[3][c];
        out[(size_t)n * 3 + c] = clip5(v);
    }
}

// ---------------- launch ----------------
extern "C" void kernel_launch(void* const* d_in, const int* in_sizes, int n_in,
                              void* d_out, int out_size)
{
    const float* z      = (const float*)d_in[0];
    const float* pos    = (const float*)d_in[1];
    const int*   ei     = (const int*)  d_in[2];
    const float* in_w   = (const float*)d_in[3];
    const float* in_b   = (const float*)d_in[4];
    const float* filt_w = (const float*)d_in[5];
    const float* filt_b = (const float*)d_in[6];
    const float* iw1    = (const float*)d_in[7];
    const float* ib1    = (const float*)d_in[8];
    const float* iw2    = (const float*)d_in[9];
    const float* ib2    = (const float*)d_in[10];
    const float* mmw    = (const float*)d_in[11];
    const float* mw1    = (const float*)d_in[12];
    const float* mb1    = (const float*)d_in[13];
    const float* mw2    = (const float*)d_in[14];
    const float* mb2    = (const float*)d_in[15];
    const float* mpw    = (const float*)d_in[16];
    const float* lng    = (const float*)d_in[17];
    const float* lnb    = (const float*)d_in[18];
    float* out = (float*)d_out;

    float *p_q, *p_h, *p_mu, *p_mu2, *p_mumix, *p_ctx, *p_xm;
    __half* p_x;
    cudaGetSymbolAddress((void**)&p_q,     g_q);
    cudaGetSymbolAddress((void**)&p_h,     g_h);
    cudaGetSymbolAddress((void**)&p_x,     g_x);
    cudaGetSymbolAddress((void**)&p_mu,    g_mu);
    cudaGetSymbolAddress((void**)&p_mu2,   g_mu2);
    cudaGetSymbolAddress((void**)&p_mumix, g_mumix);
    cudaGetSymbolAddress((void**)&p_ctx,   g_ctx);
    cudaGetSymbolAddress((void**)&p_xm,    g_xm);

    int gy_n  = (NN + 127) / 128;        // 157
    int gy_3n = (3 * NN + 127) / 128;    // 469

    init_bufs<<<(NN + 255) / 256, 256>>>();
    csr_count<<<(NE + 255) / 256, 256>>>(ei);
    csr_scan<<<1, 1024>>>();
    csr_fill<<<(NE + 255) / 256, 256>>>(ei);

    tgemm<1,false><<<dim3(1, gy_n), 256>>>(z, in_w, in_b, p_q, NN, 64, DD);
    edge_pre<<<(NE + 7) / 8, 256>>>(pos, ei, filt_w, filt_b);

    float* mu_in = p_mu;
    float* mu_out = p_mu2;
    for (int l = 0; l < LNUM; l++) {
        tgemm<1,false><<<dim3(1, gy_n), 256>>>(p_q, iw1 + (size_t)l * DD * DD, ib1 + (size_t)l * DD,
                                               p_h, NN, DD, DD);
        tgemm<0,true><<<dim3(3, gy_n), 256>>>(p_h, iw2 + (size_t)l * DD * DD3, ib2 + (size_t)l * DD3,
                                              (float*)p_x, NN, DD, DD3);
        if (l == 0)
            gather_msg<true><<<NN / 2, 128>>>(mu_in, mu_out);
        else
            gather_msg<false><<<NN / 2, 128>>>(mu_in, mu_out);
        tgemm<0,false><<<dim3(2, gy_3n), 256>>>(mu_out, mmw + (size_t)l * DD * 256, nullptr,
                                                p_mumix, 3 * NN, DD, 256);
        reduce_mix<<<NN, 128>>>();
        tgemm<1,false><<<dim3(1, gy_n), 256>>>(p_ctx, mw1 + (size_t)l * 256 * DD, mb1 + (size_t)l * DD,
                                               p_h, NN, 256, DD);
        tgemm<0,false><<<dim3(3, gy_n), 256>>>(p_h, mw2 + (size_t)l * DD * DD3, mb2 + (size_t)l * DD3,
                                               p_xm, NN, DD, DD3);
        update_node<<<NN, 128>>>(mu_out);
        float* tmp = mu_in; mu_in = mu_out; mu_out = tmp;
    }

    layernorm_out<<<NN, 128>>>(lng, lnb, out);
    pos_gather<<<NN, 128>>>(mu_in, mpw, out + (size_t)NN * DD);
}